// round 1
// baseline (speedup 1.0000x reference)
#include <cuda_runtime.h>
#include <cuda_bf16.h>

// Problem constants
#define S_LEN 2048
#define D_DIM 1024
#define H_NUM 16
#define DH 64
#define LN_EPS 1e-5f

// ---------------------------------------------------------------------------
// Scratch (device globals; no allocation allowed)
// ---------------------------------------------------------------------------
__device__ float g_Q[S_LEN * D_DIM];
__device__ float g_K[S_LEN * D_DIM];
__device__ float g_V[S_LEN * D_DIM];
__device__ float g_attn[S_LEN * D_DIM];
__device__ float g_res[S_LEN * D_DIM];

// ---------------------------------------------------------------------------
// GEMM (NT): C[m,n] = sum_k A[m,k] * B[n,k]  (+ optional residual)
// A: [M,K] row-major, B: [N,K] row-major.
// Tiles: BM=64, BN=128, BK=16. 256 threads, each computes 4x8 microtile.
// ---------------------------------------------------------------------------
#define GBM 64
#define GBN 128
#define GBK 16

__global__ __launch_bounds__(256) void gemm_nt_kernel(
    const float* __restrict__ A, const float* __restrict__ B,
    const float* __restrict__ resid, float* __restrict__ C,
    int M, int N, int K)
{
    __shared__ float As[GBK * GBM];   // As[k][m]
    __shared__ float Bs[GBK * GBN];   // Bs[k][n]

    const int tid = threadIdx.x;
    const int bm = blockIdx.y;
    const int bn = blockIdx.x;
    const int ty = tid >> 4;   // 0..15 -> 4 rows each
    const int tx = tid & 15;   // 0..15 -> 8 cols each

    const float* Ab = A + (size_t)bm * GBM * K;
    const float* Bb = B + (size_t)bn * GBN * K;

    float acc[4][8];
#pragma unroll
    for (int i = 0; i < 4; i++)
#pragma unroll
        for (int j = 0; j < 8; j++) acc[i][j] = 0.0f;

    for (int kt = 0; kt < K; kt += GBK) {
        // Load A tile: 64 rows x 16 cols = 256 float4 -> 1 per thread
        {
            int row = tid >> 2, c4 = tid & 3;
            float4 av = *(const float4*)(Ab + (size_t)row * K + kt + c4 * 4);
            As[(c4 * 4 + 0) * GBM + row] = av.x;
            As[(c4 * 4 + 1) * GBM + row] = av.y;
            As[(c4 * 4 + 2) * GBM + row] = av.z;
            As[(c4 * 4 + 3) * GBM + row] = av.w;
        }
        // Load B tile: 128 rows x 16 cols = 512 float4 -> 2 per thread
#pragma unroll
        for (int i = 0; i < 2; i++) {
            int idx = tid + i * 256;
            int row = idx >> 2, c4 = idx & 3;
            float4 bv = *(const float4*)(Bb + (size_t)row * K + kt + c4 * 4);
            Bs[(c4 * 4 + 0) * GBN + row] = bv.x;
            Bs[(c4 * 4 + 1) * GBN + row] = bv.y;
            Bs[(c4 * 4 + 2) * GBN + row] = bv.z;
            Bs[(c4 * 4 + 3) * GBN + row] = bv.w;
        }
        __syncthreads();

#pragma unroll
        for (int kk = 0; kk < GBK; kk++) {
            float4 a0 = *(const float4*)(As + kk * GBM + ty * 4);
            float4 b0 = *(const float4*)(Bs + kk * GBN + tx * 8);
            float4 b1 = *(const float4*)(Bs + kk * GBN + tx * 8 + 4);
            float a[4] = {a0.x, a0.y, a0.z, a0.w};
            float b[8] = {b0.x, b0.y, b0.z, b0.w, b1.x, b1.y, b1.z, b1.w};
#pragma unroll
            for (int i = 0; i < 4; i++)
#pragma unroll
                for (int j = 0; j < 8; j++)
                    acc[i][j] = fmaf(a[i], b[j], acc[i][j]);
        }
        __syncthreads();
    }

    // Epilogue
#pragma unroll
    for (int i = 0; i < 4; i++) {
        int row = bm * GBM + ty * 4 + i;
#pragma unroll
        for (int j = 0; j < 8; j++) {
            int col = bn * GBN + tx * 8 + j;
            float v = acc[i][j];
            if (resid) v += resid[(size_t)row * N + col];
            C[(size_t)row * N + col] = v;
        }
    }
}

// ---------------------------------------------------------------------------
// Fused attention per head, flash-style with online softmax.
// Grid: (S/64, H). Block: 256 threads.
// Each block: 64 query rows of head h. Iterates over 32 kv tiles of 64 keys.
// ---------------------------------------------------------------------------
#define AT_PAD 65
#define ATT_SMEM_BYTES ((4 * 64 * AT_PAD + 3 * 64) * 4)

__global__ __launch_bounds__(256) void attn_kernel(
    const float* __restrict__ Q, const float* __restrict__ Kp,
    const float* __restrict__ Vp, const float* __restrict__ bias,
    const unsigned int* __restrict__ mask, float* __restrict__ O)
{
    extern __shared__ float sm[];
    float* qs  = sm;                   // [64][65]
    float* ks  = qs + 64 * AT_PAD;     // [64][65]
    float* vs  = ks + 64 * AT_PAD;     // [64][65]
    float* sc  = vs + 64 * AT_PAD;     // [64][65]
    float* m_s = sc + 64 * AT_PAD;     // [64]
    float* l_s = m_s + 64;             // [64]
    float* al  = l_s + 64;             // [64]

    const int h  = blockIdx.y;
    const int q0 = blockIdx.x * 64;
    const int tid = threadIdx.x;
    const int ty = tid >> 4;   // 0..15
    const int tx = tid & 15;   // 0..15
    const float scale = 0.125f;  // 1/sqrt(64)

    // Load q tile (pre-scaled): 64 rows x 64 cols = 1024 float4 -> 4/thread
#pragma unroll
    for (int i = 0; i < 4; i++) {
        int idx = tid + i * 256;
        int row = idx >> 4, c4 = idx & 15;
        float4 v = *(const float4*)(Q + (size_t)(q0 + row) * D_DIM + h * DH + c4 * 4);
        float* dst = qs + row * AT_PAD + c4 * 4;
        dst[0] = v.x * scale; dst[1] = v.y * scale;
        dst[2] = v.z * scale; dst[3] = v.w * scale;
    }
    if (tid < 64) { m_s[tid] = -1e30f; l_s[tid] = 0.0f; }

    float o[4][4];
#pragma unroll
    for (int i = 0; i < 4; i++)
#pragma unroll
        for (int j = 0; j < 4; j++) o[i][j] = 0.0f;

    __syncthreads();

    for (int j0 = 0; j0 < S_LEN; j0 += 64) {
        // Load K, V tiles
#pragma unroll
        for (int i = 0; i < 4; i++) {
            int idx = tid + i * 256;
            int row = idx >> 4, c4 = idx & 15;
            float4 kv = *(const float4*)(Kp + (size_t)(j0 + row) * D_DIM + h * DH + c4 * 4);
            float* kd = ks + row * AT_PAD + c4 * 4;
            kd[0] = kv.x; kd[1] = kv.y; kd[2] = kv.z; kd[3] = kv.w;
            float4 vv = *(const float4*)(Vp + (size_t)(j0 + row) * D_DIM + h * DH + c4 * 4);
            float* vd = vs + row * AT_PAD + c4 * 4;
            vd[0] = vv.x; vd[1] = vv.y; vd[2] = vv.z; vd[3] = vv.w;
        }
        __syncthreads();

        // Scores: s[4][4] = q . k (q pre-scaled)
        float s[4][4];
#pragma unroll
        for (int i = 0; i < 4; i++)
#pragma unroll
            for (int j = 0; j < 4; j++) s[i][j] = 0.0f;

#pragma unroll 8
        for (int k = 0; k < 64; k++) {
            float a[4], b[4];
#pragma unroll
            for (int i = 0; i < 4; i++) a[i] = qs[(ty * 4 + i) * AT_PAD + k];
#pragma unroll
            for (int j = 0; j < 4; j++) b[j] = ks[(tx * 4 + j) * AT_PAD + k];
#pragma unroll
            for (int i = 0; i < 4; i++)
#pragma unroll
                for (int j = 0; j < 4; j++)
                    s[i][j] = fmaf(a[i], b[j], s[i][j]);
        }

        // Bias + mask, store to sc
#pragma unroll
        for (int i = 0; i < 4; i++) {
            int r = ty * 4 + i;
            int gq = q0 + r;
            const float* brow = bias + (size_t)gq * (H_NUM * S_LEN) + (size_t)h * S_LEN + j0;
            const unsigned int* mrow = mask + (size_t)gq * S_LEN + j0;
#pragma unroll
            for (int j = 0; j < 4; j++) {
                int c = tx * 4 + j;
                float v = s[i][j] + brow[c];
                v = (mrow[c] != 0u) ? v : -1e30f;
                sc[r * AT_PAD + c] = v;
            }
        }
        __syncthreads();

        // Online softmax: warp w owns rows w*8 .. w*8+7
        {
            int warp = tid >> 5, lane = tid & 31;
#pragma unroll
            for (int qq = 0; qq < 8; qq++) {
                int r = warp * 8 + qq;
                float s0 = sc[r * AT_PAD + lane];
                float s1 = sc[r * AT_PAD + lane + 32];
                float mx = fmaxf(s0, s1);
#pragma unroll
                for (int off = 16; off > 0; off >>= 1)
                    mx = fmaxf(mx, __shfl_xor_sync(0xffffffffu, mx, off));
                float mo = m_s[r];
                float mn = fmaxf(mo, mx);
                float p0 = __expf(s0 - mn);
                float p1 = __expf(s1 - mn);
                float sum = p0 + p1;
#pragma unroll
                for (int off = 16; off > 0; off >>= 1)
                    sum += __shfl_xor_sync(0xffffffffu, sum, off);
                if (lane == 0) {
                    float a = __expf(mo - mn);
                    al[r] = a;
                    l_s[r] = l_s[r] * a + sum;
                    m_s[r] = mn;
                }
                sc[r * AT_PAD + lane] = p0;
                sc[r * AT_PAD + lane + 32] = p1;
            }
        }
        __syncthreads();

        // Rescale accumulators, then PV
        float a4[4];
#pragma unroll
        for (int i = 0; i < 4; i++) a4[i] = al[ty * 4 + i];
#pragma unroll
        for (int i = 0; i < 4; i++)
#pragma unroll
            for (int j = 0; j < 4; j++) o[i][j] *= a4[i];

#pragma unroll 8
        for (int k = 0; k < 64; k++) {
            float p[4], vv[4];
#pragma unroll
            for (int i = 0; i < 4; i++) p[i] = sc[(ty * 4 + i) * AT_PAD + k];
#pragma unroll
            for (int j = 0; j < 4; j++) vv[j] = vs[k * AT_PAD + tx * 4 + j];
#pragma unroll
            for (int i = 0; i < 4; i++)
#pragma unroll
                for (int j = 0; j < 4; j++)
                    o[i][j] = fmaf(p[i], vv[j], o[i][j]);
        }
        __syncthreads();
    }

    // Normalize and write out: O[q, h*DH + d]
#pragma unroll
    for (int i = 0; i < 4; i++) {
        int r = ty * 4 + i;
        float inv = 1.0f / l_s[r];
#pragma unroll
        for (int j = 0; j < 4; j++) {
            O[(size_t)(q0 + r) * D_DIM + h * DH + tx * 4 + j] = o[i][j] * inv;
        }
    }
}

// ---------------------------------------------------------------------------
// LayerNorm: one block per row (1024 elems, 256 threads x 4)
// ---------------------------------------------------------------------------
__device__ __forceinline__ float block_reduce_sum(float v) {
    __shared__ float red[8];
    int lane = threadIdx.x & 31, w = threadIdx.x >> 5;
#pragma unroll
    for (int o = 16; o > 0; o >>= 1) v += __shfl_xor_sync(0xffffffffu, v, o);
    __syncthreads();                // protect red across reuses
    if (lane == 0) red[w] = v;
    __syncthreads();
    float t = 0.0f;
#pragma unroll
    for (int i = 0; i < 8; i++) t += red[i];
    return t;
}

__global__ __launch_bounds__(256) void ln_kernel(
    const float* __restrict__ res, const float* __restrict__ w,
    const float* __restrict__ b, float* __restrict__ out)
{
    int row = blockIdx.x;
    int tid = threadIdx.x;
    const float* r = res + (size_t)row * D_DIM;

    float4 x4 = *(const float4*)(r + tid * 4);
    float sum = x4.x + x4.y + x4.z + x4.w;
    sum = block_reduce_sum(sum);
    float mean = sum * (1.0f / D_DIM);

    float d0 = x4.x - mean, d1 = x4.y - mean, d2 = x4.z - mean, d3 = x4.w - mean;
    float sq = d0 * d0 + d1 * d1 + d2 * d2 + d3 * d3;
    sq = block_reduce_sum(sq);
    float inv = rsqrtf(sq * (1.0f / D_DIM) + LN_EPS);

    float4 w4 = *(const float4*)(w + tid * 4);
    float4 b4 = *(const float4*)(b + tid * 4);
    float4 o4;
    o4.x = d0 * inv * w4.x + b4.x;
    o4.y = d1 * inv * w4.y + b4.y;
    o4.z = d2 * inv * w4.z + b4.z;
    o4.w = d3 * inv * w4.w + b4.w;
    *(float4*)(out + (size_t)row * D_DIM + tid * 4) = o4;
}

// ---------------------------------------------------------------------------
// Launch
// ---------------------------------------------------------------------------
extern "C" void kernel_launch(void* const* d_in, const int* in_sizes, int n_in,
                              void* d_out, int out_size)
{
    (void)in_sizes; (void)n_in; (void)out_size;

    const float*        x    = (const float*)d_in[0];
    const float*        bias = (const float*)d_in[1];
    const unsigned int* mask = (const unsigned int*)d_in[2];
    const float*        Wq   = (const float*)d_in[3];
    const float*        Wk   = (const float*)d_in[4];
    const float*        Wv   = (const float*)d_in[5];
    const float*        Wo   = (const float*)d_in[6];
    const float*        lnw  = (const float*)d_in[7];
    const float*        lnb  = (const float*)d_in[8];
    float*              out  = (float*)d_out;

    void *pQ, *pK, *pV, *pA, *pR;
    cudaGetSymbolAddress(&pQ, g_Q);
    cudaGetSymbolAddress(&pK, g_K);
    cudaGetSymbolAddress(&pV, g_V);
    cudaGetSymbolAddress(&pA, g_attn);
    cudaGetSymbolAddress(&pR, g_res);

    dim3 gg(D_DIM / GBN, S_LEN / GBM);   // (8, 32)

    gemm_nt_kernel<<<gg, 256>>>(x, Wq, nullptr, (float*)pQ, S_LEN, D_DIM, D_DIM);
    gemm_nt_kernel<<<gg, 256>>>(x, Wk, nullptr, (float*)pK, S_LEN, D_DIM, D_DIM);
    gemm_nt_kernel<<<gg, 256>>>(x, Wv, nullptr, (float*)pV, S_LEN, D_DIM, D_DIM);

    cudaFuncSetAttribute(attn_kernel, cudaFuncAttributeMaxDynamicSharedMemorySize,
                         ATT_SMEM_BYTES);
    attn_kernel<<<dim3(S_LEN / 64, H_NUM), 256, ATT_SMEM_BYTES>>>(
        (const float*)pQ, (const float*)pK, (const float*)pV, bias, mask, (float*)pA);

    gemm_nt_kernel<<<gg, 256>>>((const float*)pA, Wo, x, (float*)pR, S_LEN, D_DIM, D_DIM);

    ln_kernel<<<S_LEN, 256>>>((const float*)pR, lnw, lnb, out);
}

// round 3
// speedup vs baseline: 1.5732x; 1.5732x over previous
#include <cuda_runtime.h>
#include <cuda_bf16.h>
#include <cstdint>

// Problem constants
#define S_LEN 2048
#define D_DIM 1024
#define H_NUM 16
#define DH 64
#define LN_EPS 1e-5f

// ---------------------------------------------------------------------------
// Warp MMA helpers (plain sm_103 PTX: ldmatrix + mma.sync + cp.async)
// ---------------------------------------------------------------------------
__device__ __forceinline__ uint32_t smem_u32(const void* p) {
    uint32_t a;
    asm("{ .reg .u64 t; cvta.to.shared.u64 t, %1; cvt.u32.u64 %0, t; }"
        : "=r"(a) : "l"(p));
    return a;
}

__device__ __forceinline__ void ldsm4(uint32_t* r, uint32_t a) {
    asm volatile("ldmatrix.sync.aligned.m8n8.x4.shared.b16 {%0,%1,%2,%3}, [%4];"
                 : "=r"(r[0]), "=r"(r[1]), "=r"(r[2]), "=r"(r[3]) : "r"(a));
}

__device__ __forceinline__ void mma16816(float* c, const uint32_t* a, const uint32_t* b) {
    asm volatile("mma.sync.aligned.m16n8k16.row.col.f32.bf16.bf16.f32 "
                 "{%0,%1,%2,%3}, {%4,%5,%6,%7}, {%8,%9}, {%0,%1,%2,%3};"
                 : "+f"(c[0]), "+f"(c[1]), "+f"(c[2]), "+f"(c[3])
                 : "r"(a[0]), "r"(a[1]), "r"(a[2]), "r"(a[3]),
                   "r"(b[0]), "r"(b[1]));
}

__device__ __forceinline__ void cp_async16(uint32_t dst, const void* src) {
    asm volatile("cp.async.cg.shared.global [%0], [%1], 16;" :: "r"(dst), "l"(src) : "memory");
}
__device__ __forceinline__ void cp_async_commit() { asm volatile("cp.async.commit_group;" ::: "memory"); }
__device__ __forceinline__ void cp_async_wait1()  { asm volatile("cp.async.wait_group 1;" ::: "memory"); }
__device__ __forceinline__ void cp_async_wait0()  { asm volatile("cp.async.wait_group 0;" ::: "memory"); }

// ---------------------------------------------------------------------------
// Scratch (device globals)
// ---------------------------------------------------------------------------
__device__ float g_Q[S_LEN * D_DIM];
__device__ float g_K[S_LEN * D_DIM];
__device__ float g_V[S_LEN * D_DIM];
__device__ float g_attn[S_LEN * D_DIM];
__device__ float g_res[S_LEN * D_DIM];

__device__ __nv_bfloat16 g_ah[S_LEN * D_DIM];   // A hi
__device__ __nv_bfloat16 g_al[S_LEN * D_DIM];   // A lo
__device__ __nv_bfloat16 g_wh[D_DIM * D_DIM];   // W hi
__device__ __nv_bfloat16 g_wl[D_DIM * D_DIM];   // W lo

// ---------------------------------------------------------------------------
// fp32 -> (bf16 hi, bf16 lo) split
// ---------------------------------------------------------------------------
__global__ __launch_bounds__(256) void split_bf16_kernel(
    const float* __restrict__ in, __nv_bfloat16* __restrict__ hi,
    __nv_bfloat16* __restrict__ lo, int n)
{
    int i = (blockIdx.x * 256 + threadIdx.x) * 4;
    if (i >= n) return;
    float4 v = *(const float4*)(in + i);
    __nv_bfloat16 h0 = __float2bfloat16(v.x);
    __nv_bfloat16 h1 = __float2bfloat16(v.y);
    __nv_bfloat16 h2 = __float2bfloat16(v.z);
    __nv_bfloat16 h3 = __float2bfloat16(v.w);
    __nv_bfloat16 l0 = __float2bfloat16(v.x - __bfloat162float(h0));
    __nv_bfloat16 l1 = __float2bfloat16(v.y - __bfloat162float(h1));
    __nv_bfloat16 l2 = __float2bfloat16(v.z - __bfloat162float(h2));
    __nv_bfloat16 l3 = __float2bfloat16(v.w - __bfloat162float(h3));
    __nv_bfloat162* hp = (__nv_bfloat162*)(hi + i);
    __nv_bfloat162* lp = (__nv_bfloat162*)(lo + i);
    hp[0] = __nv_bfloat162(h0, h1); hp[1] = __nv_bfloat162(h2, h3);
    lp[0] = __nv_bfloat162(l0, l1); lp[1] = __nv_bfloat162(l2, l3);
}

// ---------------------------------------------------------------------------
// bf16 hi/lo GEMM via mma.sync: C[m,n] = sum_k A[m,k]*B[n,k] (+resid)
// Tile 128x128, BK=32. 8 warps (2x4), each computes 64x32.
// A.B ~= Ah.Bh + Ah.Bl + Al.Bh
// Smem: 4 tiles (Ah,Al,Bh,Bl) of 128 rows x 80B pitch, double buffered.
// ---------------------------------------------------------------------------
#define MPITCH 80
#define MTILE_B (128 * MPITCH)       // 10240
#define MBUF_B  (4 * MTILE_B)        // 40960
#define GEMM_SMEM (2 * MBUF_B)       // 81920

__global__ __launch_bounds__(256) void gemm_mma_kernel(
    const __nv_bfloat16* __restrict__ Ahi, const __nv_bfloat16* __restrict__ Alo,
    const __nv_bfloat16* __restrict__ Bhi, const __nv_bfloat16* __restrict__ Blo,
    const float* __restrict__ resid, float* __restrict__ C, int M, int N, int K)
{
    extern __shared__ char smem[];
    const uint32_t sb = smem_u32(smem);
    const int tid  = threadIdx.x;
    const int wid  = tid >> 5;
    const int lane = tid & 31;
    const int wm   = wid >> 2;   // 0..1
    const int wn   = wid & 3;    // 0..3

    const int m0 = blockIdx.y * 128;
    const int n0 = blockIdx.x * 128;

    const __nv_bfloat16* srcs[4] = {
        Ahi + (size_t)m0 * K, Alo + (size_t)m0 * K,
        Bhi + (size_t)n0 * K, Blo + (size_t)n0 * K };

    float acc[4][4][4];
#pragma unroll
    for (int i = 0; i < 4; i++)
#pragma unroll
        for (int j = 0; j < 4; j++)
#pragma unroll
            for (int r = 0; r < 4; r++) acc[i][j][r] = 0.0f;

    const int NCH = K / 32;

    // chunk loader: 4 tiles x 128 rows x 2 chunks(16B)... = 2048 16B chunks
    auto load_chunk = [&](int ch) {
        const int k0 = ch * 32;
        const uint32_t base = sb + (ch & 1) * MBUF_B;
#pragma unroll
        for (int t = 0; t < 8; t++) {
            int idx = tid + t * 256;
            int tile = idx >> 9;
            int rem = idx & 511;
            int row = rem >> 2;
            int c = rem & 3;
            cp_async16(base + tile * MTILE_B + row * MPITCH + c * 16,
                       srcs[tile] + (size_t)row * K + k0 + c * 8);
        }
        cp_async_commit();
    };

    load_chunk(0);

    for (int ch = 0; ch < NCH; ch++) {
        if (ch + 1 < NCH) { load_chunk(ch + 1); cp_async_wait1(); }
        else              { cp_async_wait0(); }
        __syncthreads();

        const uint32_t base = sb + (ch & 1) * MBUF_B;
        const uint32_t pAh = base;
        const uint32_t pAl = base + MTILE_B;
        const uint32_t pBh = base + 2 * MTILE_B;
        const uint32_t pBl = base + 3 * MTILE_B;

        // lane-specific ldmatrix source rows
        const int arow = wm * 64 + (lane & 15);
        const int brow = wn * 32 + ((lane >> 4) & 1) * 8 + (lane & 7);

#pragma unroll
        for (int ks = 0; ks < 2; ks++) {
            const int akk = ks * 16 + (lane >> 4) * 8;          // A: k-half by lane/16
            const int bkk = ks * 16 + ((lane >> 3) & 1) * 8;    // B: k-half by (lane/8)&1

            uint32_t ah[4][4], alr[4][4], bh[4][2], bl[4][2];
#pragma unroll
            for (int mt = 0; mt < 4; mt++) {
                uint32_t off = (uint32_t)(arow + mt * 16) * MPITCH + akk * 2;
                ldsm4(ah[mt],  pAh + off);
                ldsm4(alr[mt], pAl + off);
            }
#pragma unroll
            for (int np = 0; np < 2; np++) {
                uint32_t off = (uint32_t)(brow + np * 16) * MPITCH + bkk * 2;
                uint32_t r[4];
                ldsm4(r, pBh + off);
                bh[np * 2][0] = r[0]; bh[np * 2][1] = r[1];
                bh[np * 2 + 1][0] = r[2]; bh[np * 2 + 1][1] = r[3];
                ldsm4(r, pBl + off);
                bl[np * 2][0] = r[0]; bl[np * 2][1] = r[1];
                bl[np * 2 + 1][0] = r[2]; bl[np * 2 + 1][1] = r[3];
            }
#pragma unroll
            for (int mt = 0; mt < 4; mt++)
#pragma unroll
                for (int nt = 0; nt < 4; nt++) {
                    mma16816(acc[mt][nt], ah[mt],  bh[nt]);
                    mma16816(acc[mt][nt], ah[mt],  bl[nt]);
                    mma16816(acc[mt][nt], alr[mt], bh[nt]);
                }
        }
        __syncthreads();
    }

    // Epilogue: c0,c1 -> (row, col..col+1); c2,c3 -> (row+8, col..col+1)
#pragma unroll
    for (int mt = 0; mt < 4; mt++) {
        int row = m0 + wm * 64 + mt * 16 + (lane >> 2);
#pragma unroll
        for (int nt = 0; nt < 4; nt++) {
            int col = n0 + wn * 32 + nt * 8 + (lane & 3) * 2;
            float2 v0 = make_float2(acc[mt][nt][0], acc[mt][nt][1]);
            float2 v1 = make_float2(acc[mt][nt][2], acc[mt][nt][3]);
            if (resid) {
                float2 r0 = *(const float2*)(resid + (size_t)row * N + col);
                float2 r1 = *(const float2*)(resid + (size_t)(row + 8) * N + col);
                v0.x += r0.x; v0.y += r0.y;
                v1.x += r1.x; v1.y += r1.y;
            }
            *(float2*)(C + (size_t)row * N + col) = v0;
            *(float2*)(C + (size_t)(row + 8) * N + col) = v1;
        }
    }
}

// ---------------------------------------------------------------------------
// Fused attention per head (unchanged, known-good)
// ---------------------------------------------------------------------------
#define AT_PAD 65
#define ATT_SMEM_BYTES ((4 * 64 * AT_PAD + 3 * 64) * 4)

__global__ __launch_bounds__(256) void attn_kernel(
    const float* __restrict__ Q, const float* __restrict__ Kp,
    const float* __restrict__ Vp, const float* __restrict__ bias,
    const unsigned int* __restrict__ mask, float* __restrict__ O)
{
    extern __shared__ float sm[];
    float* qs  = sm;
    float* ks  = qs + 64 * AT_PAD;
    float* vs  = ks + 64 * AT_PAD;
    float* sc  = vs + 64 * AT_PAD;
    float* m_s = sc + 64 * AT_PAD;
    float* l_s = m_s + 64;
    float* al  = l_s + 64;

    const int h  = blockIdx.y;
    const int q0 = blockIdx.x * 64;
    const int tid = threadIdx.x;
    const int ty = tid >> 4;
    const int tx = tid & 15;
    const float scale = 0.125f;

#pragma unroll
    for (int i = 0; i < 4; i++) {
        int idx = tid + i * 256;
        int row = idx >> 4, c4 = idx & 15;
        float4 v = *(const float4*)(Q + (size_t)(q0 + row) * D_DIM + h * DH + c4 * 4);
        float* dst = qs + row * AT_PAD + c4 * 4;
        dst[0] = v.x * scale; dst[1] = v.y * scale;
        dst[2] = v.z * scale; dst[3] = v.w * scale;
    }
    if (tid < 64) { m_s[tid] = -1e30f; l_s[tid] = 0.0f; }

    float o[4][4];
#pragma unroll
    for (int i = 0; i < 4; i++)
#pragma unroll
        for (int j = 0; j < 4; j++) o[i][j] = 0.0f;

    __syncthreads();

    for (int j0 = 0; j0 < S_LEN; j0 += 64) {
#pragma unroll
        for (int i = 0; i < 4; i++) {
            int idx = tid + i * 256;
            int row = idx >> 4, c4 = idx & 15;
            float4 kv = *(const float4*)(Kp + (size_t)(j0 + row) * D_DIM + h * DH + c4 * 4);
            float* kd = ks + row * AT_PAD + c4 * 4;
            kd[0] = kv.x; kd[1] = kv.y; kd[2] = kv.z; kd[3] = kv.w;
            float4 vv = *(const float4*)(Vp + (size_t)(j0 + row) * D_DIM + h * DH + c4 * 4);
            float* vd = vs + row * AT_PAD + c4 * 4;
            vd[0] = vv.x; vd[1] = vv.y; vd[2] = vv.z; vd[3] = vv.w;
        }
        __syncthreads();

        float s[4][4];
#pragma unroll
        for (int i = 0; i < 4; i++)
#pragma unroll
            for (int j = 0; j < 4; j++) s[i][j] = 0.0f;

#pragma unroll 8
        for (int k = 0; k < 64; k++) {
            float a[4], b[4];
#pragma unroll
            for (int i = 0; i < 4; i++) a[i] = qs[(ty * 4 + i) * AT_PAD + k];
#pragma unroll
            for (int j = 0; j < 4; j++) b[j] = ks[(tx * 4 + j) * AT_PAD + k];
#pragma unroll
            for (int i = 0; i < 4; i++)
#pragma unroll
                for (int j = 0; j < 4; j++)
                    s[i][j] = fmaf(a[i], b[j], s[i][j]);
        }

#pragma unroll
        for (int i = 0; i < 4; i++) {
            int r = ty * 4 + i;
            int gq = q0 + r;
            const float* brow = bias + (size_t)gq * (H_NUM * S_LEN) + (size_t)h * S_LEN + j0;
            const unsigned int* mrow = mask + (size_t)gq * S_LEN + j0;
#pragma unroll
            for (int j = 0; j < 4; j++) {
                int c = tx * 4 + j;
                float v = s[i][j] + brow[c];
                v = (mrow[c] != 0u) ? v : -1e30f;
                sc[r * AT_PAD + c] = v;
            }
        }
        __syncthreads();

        {
            int warp = tid >> 5, lane = tid & 31;
#pragma unroll
            for (int qq = 0; qq < 8; qq++) {
                int r = warp * 8 + qq;
                float s0 = sc[r * AT_PAD + lane];
                float s1 = sc[r * AT_PAD + lane + 32];
                float mx = fmaxf(s0, s1);
#pragma unroll
                for (int off = 16; off > 0; off >>= 1)
                    mx = fmaxf(mx, __shfl_xor_sync(0xffffffffu, mx, off));
                float mo = m_s[r];
                float mn = fmaxf(mo, mx);
                float p0 = __expf(s0 - mn);
                float p1 = __expf(s1 - mn);
                float sum = p0 + p1;
#pragma unroll
                for (int off = 16; off > 0; off >>= 1)
                    sum += __shfl_xor_sync(0xffffffffu, sum, off);
                if (lane == 0) {
                    float a = __expf(mo - mn);
                    al[r] = a;
                    l_s[r] = l_s[r] * a + sum;
                    m_s[r] = mn;
                }
                sc[r * AT_PAD + lane] = p0;
                sc[r * AT_PAD + lane + 32] = p1;
            }
        }
        __syncthreads();

        float a4[4];
#pragma unroll
        for (int i = 0; i < 4; i++) a4[i] = al[ty * 4 + i];
#pragma unroll
        for (int i = 0; i < 4; i++)
#pragma unroll
            for (int j = 0; j < 4; j++) o[i][j] *= a4[i];

#pragma unroll 8
        for (int k = 0; k < 64; k++) {
            float p[4], vv[4];
#pragma unroll
            for (int i = 0; i < 4; i++) p[i] = sc[(ty * 4 + i) * AT_PAD + k];
#pragma unroll
            for (int j = 0; j < 4; j++) vv[j] = vs[k * AT_PAD + tx * 4 + j];
#pragma unroll
            for (int i = 0; i < 4; i++)
#pragma unroll
                for (int j = 0; j < 4; j++)
                    o[i][j] = fmaf(p[i], vv[j], o[i][j]);
        }
        __syncthreads();
    }

#pragma unroll
    for (int i = 0; i < 4; i++) {
        int r = ty * 4 + i;
        float inv = 1.0f / l_s[r];
#pragma unroll
        for (int j = 0; j < 4; j++) {
            O[(size_t)(q0 + r) * D_DIM + h * DH + tx * 4 + j] = o[i][j] * inv;
        }
    }
}

// ---------------------------------------------------------------------------
// LayerNorm (unchanged)
// ---------------------------------------------------------------------------
__device__ __forceinline__ float block_reduce_sum(float v) {
    __shared__ float red[8];
    int lane = threadIdx.x & 31, w = threadIdx.x >> 5;
#pragma unroll
    for (int o = 16; o > 0; o >>= 1) v += __shfl_xor_sync(0xffffffffu, v, o);
    __syncthreads();
    if (lane == 0) red[w] = v;
    __syncthreads();
    float t = 0.0f;
#pragma unroll
    for (int i = 0; i < 8; i++) t += red[i];
    return t;
}

__global__ __launch_bounds__(256) void ln_kernel(
    const float* __restrict__ res, const float* __restrict__ w,
    const float* __restrict__ b, float* __restrict__ out)
{
    int row = blockIdx.x;
    int tid = threadIdx.x;
    const float* r = res + (size_t)row * D_DIM;

    float4 x4 = *(const float4*)(r + tid * 4);
    float sum = x4.x + x4.y + x4.z + x4.w;
    sum = block_reduce_sum(sum);
    float mean = sum * (1.0f / D_DIM);

    float d0 = x4.x - mean, d1 = x4.y - mean, d2 = x4.z - mean, d3 = x4.w - mean;
    float sq = d0 * d0 + d1 * d1 + d2 * d2 + d3 * d3;
    sq = block_reduce_sum(sq);
    float inv = rsqrtf(sq * (1.0f / D_DIM) + LN_EPS);

    float4 w4 = *(const float4*)(w + tid * 4);
    float4 b4 = *(const float4*)(b + tid * 4);
    float4 o4;
    o4.x = d0 * inv * w4.x + b4.x;
    o4.y = d1 * inv * w4.y + b4.y;
    o4.z = d2 * inv * w4.z + b4.z;
    o4.w = d3 * inv * w4.w + b4.w;
    *(float4*)(out + (size_t)row * D_DIM + tid * 4) = o4;
}

// ---------------------------------------------------------------------------
// Launch
// ---------------------------------------------------------------------------
extern "C" void kernel_launch(void* const* d_in, const int* in_sizes, int n_in,
                              void* d_out, int out_size)
{
    (void)in_sizes; (void)n_in; (void)out_size;

    const float*        x    = (const float*)d_in[0];
    const float*        bias = (const float*)d_in[1];
    const unsigned int* mask = (const unsigned int*)d_in[2];
    const float*        Wq   = (const float*)d_in[3];
    const float*        Wk   = (const float*)d_in[4];
    const float*        Wv   = (const float*)d_in[5];
    const float*        Wo   = (const float*)d_in[6];
    const float*        lnw  = (const float*)d_in[7];
    const float*        lnb  = (const float*)d_in[8];
    float*              out  = (float*)d_out;

    void *pQ, *pK, *pV, *pA, *pR, *pAh, *pAl, *pWh, *pWl;
    cudaGetSymbolAddress(&pQ, g_Q);
    cudaGetSymbolAddress(&pK, g_K);
    cudaGetSymbolAddress(&pV, g_V);
    cudaGetSymbolAddress(&pA, g_attn);
    cudaGetSymbolAddress(&pR, g_res);
    cudaGetSymbolAddress(&pAh, g_ah);
    cudaGetSymbolAddress(&pAl, g_al);
    cudaGetSymbolAddress(&pWh, g_wh);
    cudaGetSymbolAddress(&pWl, g_wl);

    __nv_bfloat16* ah = (__nv_bfloat16*)pAh;
    __nv_bfloat16* al = (__nv_bfloat16*)pAl;
    __nv_bfloat16* wh = (__nv_bfloat16*)pWh;
    __nv_bfloat16* wl = (__nv_bfloat16*)pWl;

    cudaFuncSetAttribute(gemm_mma_kernel, cudaFuncAttributeMaxDynamicSharedMemorySize,
                         GEMM_SMEM);
    cudaFuncSetAttribute(attn_kernel, cudaFuncAttributeMaxDynamicSharedMemorySize,
                         ATT_SMEM_BYTES);

    const int nX = S_LEN * D_DIM;     // 2M
    const int nW = D_DIM * D_DIM;     // 1M
    dim3 gt(D_DIM / 128, S_LEN / 128);  // (8, 16)

    // x -> hi/lo
    split_bf16_kernel<<<nX / 1024, 256>>>(x, ah, al, nX);

    // Q, K, V projections
    split_bf16_kernel<<<nW / 1024, 256>>>(Wq, wh, wl, nW);
    gemm_mma_kernel<<<gt, 256, GEMM_SMEM>>>(ah, al, wh, wl, nullptr, (float*)pQ,
                                            S_LEN, D_DIM, D_DIM);
    split_bf16_kernel<<<nW / 1024, 256>>>(Wk, wh, wl, nW);
    gemm_mma_kernel<<<gt, 256, GEMM_SMEM>>>(ah, al, wh, wl, nullptr, (float*)pK,
                                            S_LEN, D_DIM, D_DIM);
    split_bf16_kernel<<<nW / 1024, 256>>>(Wv, wh, wl, nW);
    gemm_mma_kernel<<<gt, 256, GEMM_SMEM>>>(ah, al, wh, wl, nullptr, (float*)pV,
                                            S_LEN, D_DIM, D_DIM);

    // Attention
    attn_kernel<<<dim3(S_LEN / 64, H_NUM), 256, ATT_SMEM_BYTES>>>(
        (const float*)pQ, (const float*)pK, (const float*)pV, bias, mask, (float*)pA);

    // Output projection + residual
    split_bf16_kernel<<<nX / 1024, 256>>>((const float*)pA, ah, al, nX);
    split_bf16_kernel<<<nW / 1024, 256>>>(Wo, wh, wl, nW);
    gemm_mma_kernel<<<gt, 256, GEMM_SMEM>>>(ah, al, wh, wl, x, (float*)pR,
                                            S_LEN, D_DIM, D_DIM);

    ln_kernel<<<S_LEN, 256>>>((const float*)pR, lnw, lnb, out);
}

// round 4
// speedup vs baseline: 3.4643x; 2.2020x over previous
#include <cuda_runtime.h>
#include <cuda_bf16.h>
#include <cstdint>

// Problem constants
#define S_LEN 2048
#define D_DIM 1024
#define H_NUM 16
#define DH 64
#define LN_EPS 1e-5f

// ---------------------------------------------------------------------------
// PTX helpers (plain sm_103: ldmatrix + mma.sync + cp.async)
// ---------------------------------------------------------------------------
__device__ __forceinline__ uint32_t smem_u32(const void* p) {
    uint32_t a;
    asm("{ .reg .u64 t; cvta.to.shared.u64 t, %1; cvt.u32.u64 %0, t; }"
        : "=r"(a) : "l"(p));
    return a;
}

__device__ __forceinline__ void ldsm4(uint32_t* r, uint32_t a) {
    asm volatile("ldmatrix.sync.aligned.m8n8.x4.shared.b16 {%0,%1,%2,%3}, [%4];"
                 : "=r"(r[0]), "=r"(r[1]), "=r"(r[2]), "=r"(r[3]) : "r"(a));
}
__device__ __forceinline__ void ldsm4t(uint32_t* r, uint32_t a) {
    asm volatile("ldmatrix.sync.aligned.m8n8.x4.trans.shared.b16 {%0,%1,%2,%3}, [%4];"
                 : "=r"(r[0]), "=r"(r[1]), "=r"(r[2]), "=r"(r[3]) : "r"(a));
}

__device__ __forceinline__ void mma16816(float* c, const uint32_t* a, const uint32_t* b) {
    asm volatile("mma.sync.aligned.m16n8k16.row.col.f32.bf16.bf16.f32 "
                 "{%0,%1,%2,%3}, {%4,%5,%6,%7}, {%8,%9}, {%0,%1,%2,%3};"
                 : "+f"(c[0]), "+f"(c[1]), "+f"(c[2]), "+f"(c[3])
                 : "r"(a[0]), "r"(a[1]), "r"(a[2]), "r"(a[3]),
                   "r"(b[0]), "r"(b[1]));
}

__device__ __forceinline__ void cp_async16(uint32_t dst, const void* src) {
    asm volatile("cp.async.cg.shared.global [%0], [%1], 16;" :: "r"(dst), "l"(src) : "memory");
}
__device__ __forceinline__ void cp_async_commit() { asm volatile("cp.async.commit_group;" ::: "memory"); }
__device__ __forceinline__ void cp_async_wait1()  { asm volatile("cp.async.wait_group 1;" ::: "memory"); }
__device__ __forceinline__ void cp_async_wait0()  { asm volatile("cp.async.wait_group 0;" ::: "memory"); }

#define SMEM_SWZ(off) ((off) ^ (((off) >> 3) & 0x70))

__device__ __forceinline__ uint32_t pack_bf16x2(float a, float b) {
    __nv_bfloat162 t = __floats2bfloat162_rn(a, b);
    return *reinterpret_cast<uint32_t*>(&t);
}

// ---------------------------------------------------------------------------
// Scratch (device globals)
// ---------------------------------------------------------------------------
__device__ __nv_bfloat16 g_qh[S_LEN * D_DIM];
__device__ __nv_bfloat16 g_ql[S_LEN * D_DIM];
__device__ __nv_bfloat16 g_kh[S_LEN * D_DIM];
__device__ __nv_bfloat16 g_kl[S_LEN * D_DIM];
__device__ __nv_bfloat16 g_vh[S_LEN * D_DIM];
__device__ __nv_bfloat16 g_vl[S_LEN * D_DIM];
__device__ __nv_bfloat16 g_xh[S_LEN * D_DIM];
__device__ __nv_bfloat16 g_xl[S_LEN * D_DIM];
__device__ __nv_bfloat16 g_ah[S_LEN * D_DIM];
__device__ __nv_bfloat16 g_al[S_LEN * D_DIM];
__device__ __nv_bfloat16 g_wh[D_DIM * D_DIM];
__device__ __nv_bfloat16 g_wl[D_DIM * D_DIM];
__device__ float g_res[S_LEN * D_DIM];

// ---------------------------------------------------------------------------
// fp32 -> (bf16 hi, bf16 lo) split
// ---------------------------------------------------------------------------
__global__ __launch_bounds__(256) void split_bf16_kernel(
    const float* __restrict__ in, __nv_bfloat16* __restrict__ hi,
    __nv_bfloat16* __restrict__ lo, int n)
{
    int i = (blockIdx.x * 256 + threadIdx.x) * 4;
    if (i >= n) return;
    float4 v = *(const float4*)(in + i);
    __nv_bfloat16 h0 = __float2bfloat16(v.x);
    __nv_bfloat16 h1 = __float2bfloat16(v.y);
    __nv_bfloat16 h2 = __float2bfloat16(v.z);
    __nv_bfloat16 h3 = __float2bfloat16(v.w);
    __nv_bfloat16 l0 = __float2bfloat16(v.x - __bfloat162float(h0));
    __nv_bfloat16 l1 = __float2bfloat16(v.y - __bfloat162float(h1));
    __nv_bfloat16 l2 = __float2bfloat16(v.z - __bfloat162float(h2));
    __nv_bfloat16 l3 = __float2bfloat16(v.w - __bfloat162float(h3));
    __nv_bfloat162* hp = (__nv_bfloat162*)(hi + i);
    __nv_bfloat162* lp = (__nv_bfloat162*)(lo + i);
    hp[0] = __nv_bfloat162(h0, h1); hp[1] = __nv_bfloat162(h2, h3);
    lp[0] = __nv_bfloat162(l0, l1); lp[1] = __nv_bfloat162(l2, l3);
}

// ---------------------------------------------------------------------------
// bf16 hi/lo GEMM via mma.sync: acc = scale * sum_k A[m,k]*B[n,k]
// Epilogue: either fp32 out (+resid) or bf16 hi/lo split out.
// Tile 128x128, BK=32. 8 warps (2x4), each 64x32.
// ---------------------------------------------------------------------------
#define MPITCH 80
#define MTILE_B (128 * MPITCH)
#define MBUF_B  (4 * MTILE_B)
#define GEMM_SMEM (2 * MBUF_B)

__global__ __launch_bounds__(256) void gemm_mma_kernel(
    const __nv_bfloat16* __restrict__ Ahi, const __nv_bfloat16* __restrict__ Alo,
    const __nv_bfloat16* __restrict__ Bhi, const __nv_bfloat16* __restrict__ Blo,
    const float* __restrict__ resid, float* __restrict__ Cf,
    __nv_bfloat16* __restrict__ Ch, __nv_bfloat16* __restrict__ Cl,
    float scale, int N, int K)
{
    extern __shared__ char smem[];
    const uint32_t sb = smem_u32(smem);
    const int tid  = threadIdx.x;
    const int wid  = tid >> 5;
    const int lane = tid & 31;
    const int wm   = wid >> 2;
    const int wn   = wid & 3;

    const int m0 = blockIdx.y * 128;
    const int n0 = blockIdx.x * 128;

    const __nv_bfloat16* srcs[4] = {
        Ahi + (size_t)m0 * K, Alo + (size_t)m0 * K,
        Bhi + (size_t)n0 * K, Blo + (size_t)n0 * K };

    float acc[4][4][4];
#pragma unroll
    for (int i = 0; i < 4; i++)
#pragma unroll
        for (int j = 0; j < 4; j++)
#pragma unroll
            for (int r = 0; r < 4; r++) acc[i][j][r] = 0.0f;

    const int NCH = K / 32;

    auto load_chunk = [&](int ch) {
        const int k0 = ch * 32;
        const uint32_t base = sb + (ch & 1) * MBUF_B;
#pragma unroll
        for (int t = 0; t < 8; t++) {
            int idx = tid + t * 256;
            int tile = idx >> 9;
            int rem = idx & 511;
            int row = rem >> 2;
            int c = rem & 3;
            cp_async16(base + tile * MTILE_B + row * MPITCH + c * 16,
                       srcs[tile] + (size_t)row * K + k0 + c * 8);
        }
        cp_async_commit();
    };

    load_chunk(0);

    for (int ch = 0; ch < NCH; ch++) {
        if (ch + 1 < NCH) { load_chunk(ch + 1); cp_async_wait1(); }
        else              { cp_async_wait0(); }
        __syncthreads();

        const uint32_t base = sb + (ch & 1) * MBUF_B;
        const uint32_t pAh = base;
        const uint32_t pAl = base + MTILE_B;
        const uint32_t pBh = base + 2 * MTILE_B;
        const uint32_t pBl = base + 3 * MTILE_B;

        const int arow = wm * 64 + (lane & 15);
        const int brow = wn * 32 + ((lane >> 4) & 1) * 8 + (lane & 7);

#pragma unroll
        for (int ks = 0; ks < 2; ks++) {
            const int akk = ks * 16 + (lane >> 4) * 8;
            const int bkk = ks * 16 + ((lane >> 3) & 1) * 8;

            uint32_t ah[4][4], alr[4][4], bh[4][2], bl[4][2];
#pragma unroll
            for (int mt = 0; mt < 4; mt++) {
                uint32_t off = (uint32_t)(arow + mt * 16) * MPITCH + akk * 2;
                ldsm4(ah[mt],  pAh + off);
                ldsm4(alr[mt], pAl + off);
            }
#pragma unroll
            for (int np = 0; np < 2; np++) {
                uint32_t off = (uint32_t)(brow + np * 16) * MPITCH + bkk * 2;
                uint32_t r[4];
                ldsm4(r, pBh + off);
                bh[np * 2][0] = r[0]; bh[np * 2][1] = r[1];
                bh[np * 2 + 1][0] = r[2]; bh[np * 2 + 1][1] = r[3];
                ldsm4(r, pBl + off);
                bl[np * 2][0] = r[0]; bl[np * 2][1] = r[1];
                bl[np * 2 + 1][0] = r[2]; bl[np * 2 + 1][1] = r[3];
            }
#pragma unroll
            for (int mt = 0; mt < 4; mt++)
#pragma unroll
                for (int nt = 0; nt < 4; nt++) {
                    mma16816(acc[mt][nt], ah[mt],  bh[nt]);
                    mma16816(acc[mt][nt], ah[mt],  bl[nt]);
                    mma16816(acc[mt][nt], alr[mt], bh[nt]);
                }
        }
        __syncthreads();
    }

    // Epilogue
#pragma unroll
    for (int mt = 0; mt < 4; mt++) {
        int row = m0 + wm * 64 + mt * 16 + (lane >> 2);
#pragma unroll
        for (int nt = 0; nt < 4; nt++) {
            int col = n0 + wn * 32 + nt * 8 + (lane & 3) * 2;
            float v0 = acc[mt][nt][0] * scale;
            float v1 = acc[mt][nt][1] * scale;
            float v2 = acc[mt][nt][2] * scale;
            float v3 = acc[mt][nt][3] * scale;
            if (Cf) {
                if (resid) {
                    float2 r0 = *(const float2*)(resid + (size_t)row * N + col);
                    float2 r1 = *(const float2*)(resid + (size_t)(row + 8) * N + col);
                    v0 += r0.x; v1 += r0.y; v2 += r1.x; v3 += r1.y;
                }
                *(float2*)(Cf + (size_t)row * N + col) = make_float2(v0, v1);
                *(float2*)(Cf + (size_t)(row + 8) * N + col) = make_float2(v2, v3);
            } else {
                float h0 = __bfloat162float(__float2bfloat16(v0));
                float h1 = __bfloat162float(__float2bfloat16(v1));
                float h2 = __bfloat162float(__float2bfloat16(v2));
                float h3 = __bfloat162float(__float2bfloat16(v3));
                *(uint32_t*)(Ch + (size_t)row * N + col)       = pack_bf16x2(h0, h1);
                *(uint32_t*)(Ch + (size_t)(row + 8) * N + col) = pack_bf16x2(h2, h3);
                *(uint32_t*)(Cl + (size_t)row * N + col)       = pack_bf16x2(v0 - h0, v1 - h1);
                *(uint32_t*)(Cl + (size_t)(row + 8) * N + col) = pack_bf16x2(v2 - h2, v3 - h3);
            }
        }
    }
}

// ---------------------------------------------------------------------------
// Tensor-core flash attention.
// Grid (S/128, H), 256 threads (8 warps), each warp owns 16 q rows.
// KV tile = 64 rows. Smem: Q stage 32KB then 2 x 32KB KV double buffer.
// QK^T ~= Qh.Kh + Ql.Kh + Qh.Kl ; PV ~= Ph.Vh + Pl.Vh + Ph.Vl
// Output written as bf16 hi/lo for the Wo GEMM.
// ---------------------------------------------------------------------------
#define ATT_SMEM 65536

__global__ __launch_bounds__(256, 1) void attn_mma_kernel(
    const __nv_bfloat16* __restrict__ Qh_, const __nv_bfloat16* __restrict__ Ql_,
    const __nv_bfloat16* __restrict__ Kh_, const __nv_bfloat16* __restrict__ Kl_,
    const __nv_bfloat16* __restrict__ Vh_, const __nv_bfloat16* __restrict__ Vl_,
    const float* __restrict__ bias, const unsigned int* __restrict__ mask,
    __nv_bfloat16* __restrict__ Oh_, __nv_bfloat16* __restrict__ Ol_)
{
    extern __shared__ char smem[];
    const uint32_t sb = smem_u32(smem);
    const int tid  = threadIdx.x;
    const int wid  = tid >> 5;
    const int lane = tid & 31;
    const int h  = blockIdx.y;
    const int q0 = blockIdx.x * 128;
    const int hoff = h * DH;

    // ---- stage Q (hi at sb, lo at sb+16384), 128 rows x 128B each ----
#pragma unroll
    for (int t = 0; t < 8; t++) {
        int half = t >> 2;                 // 0 = hi, 1 = lo
        int rem = (t & 3) * 256 + tid;     // 0..1023
        int row = rem >> 3, c = rem & 7;
        const __nv_bfloat16* src = (half ? Ql_ : Qh_) + (size_t)(q0 + row) * D_DIM + hoff + c * 8;
        cp_async16(sb + half * 16384 + SMEM_SWZ(row * 128 + c * 16), src);
    }
    cp_async_commit();
    cp_async_wait0();
    __syncthreads();

    // ---- Q fragments into registers ----
    uint32_t qh[4][4], ql[4][4];
    {
        const int qrow = wid * 16 + (lane & 15);
#pragma unroll
        for (int kc = 0; kc < 4; kc++) {
            uint32_t off = SMEM_SWZ(qrow * 128 + kc * 32 + (lane >> 4) * 16);
            ldsm4(qh[kc], sb + off);
            ldsm4(ql[kc], sb + 16384 + off);
        }
    }
    __syncthreads();

    float Oacc[8][4];
#pragma unroll
    for (int i = 0; i < 8; i++)
#pragma unroll
        for (int j = 0; j < 4; j++) Oacc[i][j] = 0.0f;
    float m0 = -1e30f, m1 = -1e30f, l0 = 0.0f, l1 = 0.0f;

    const __nv_bfloat16* kvsrc[4] = { Kh_ + hoff, Kl_ + hoff, Vh_ + hoff, Vl_ + hoff };

    auto load_kv = [&](int t) {
        const uint32_t base = sb + (t & 1) * 32768;
        const int j0 = t * 64;
#pragma unroll
        for (int i = 0; i < 8; i++) {
            int quad = i >> 1;
            int rem = (i & 1) * 256 + tid;   // 0..511
            int row = rem >> 3, c = rem & 7;
            cp_async16(base + quad * 8192 + SMEM_SWZ(row * 128 + c * 16),
                       kvsrc[quad] + (size_t)(j0 + row) * D_DIM + c * 8);
        }
        cp_async_commit();
    };

    load_kv(0);

    const int r = lane >> 2;
    const int grow0 = q0 + wid * 16 + r;
    const int grow1 = grow0 + 8;
    const float* brow0 = bias + (size_t)grow0 * (H_NUM * S_LEN) + (size_t)h * S_LEN;
    const float* brow1 = bias + (size_t)grow1 * (H_NUM * S_LEN) + (size_t)h * S_LEN;
    const unsigned int* mrow0 = mask + (size_t)grow0 * S_LEN;
    const unsigned int* mrow1 = mask + (size_t)grow1 * S_LEN;
    const int cbase = (lane & 3) * 2;

    for (int t = 0; t < S_LEN / 64; t++) {
        if (t + 1 < S_LEN / 64) { load_kv(t + 1); cp_async_wait1(); }
        else                    { cp_async_wait0(); }
        __syncthreads();

        const uint32_t base = sb + (t & 1) * 32768;
        const int j0 = t * 64;

        // ---- scores: acc[nt][4] ----
        float acc[8][4];
#pragma unroll
        for (int i = 0; i < 8; i++)
#pragma unroll
            for (int j = 0; j < 4; j++) acc[i][j] = 0.0f;

#pragma unroll
        for (int kc = 0; kc < 4; kc++) {
#pragma unroll
            for (int np = 0; np < 4; np++) {
                int krow = np * 16 + (lane >> 4) * 8 + (lane & 7);
                uint32_t koff = SMEM_SWZ(krow * 128 + kc * 32 + ((lane >> 3) & 1) * 16);
                uint32_t bh[4], bl[4];
                ldsm4(bh, base + koff);
                ldsm4(bl, base + 8192 + koff);
                mma16816(acc[2 * np],     qh[kc], bh + 0);
                mma16816(acc[2 * np],     qh[kc], bl + 0);
                mma16816(acc[2 * np],     ql[kc], bh + 0);
                mma16816(acc[2 * np + 1], qh[kc], bh + 2);
                mma16816(acc[2 * np + 1], qh[kc], bl + 2);
                mma16816(acc[2 * np + 1], ql[kc], bh + 2);
            }
        }

        // ---- bias + mask + row max ----
        float mx0 = -1e30f, mx1 = -1e30f;
#pragma unroll
        for (int nt = 0; nt < 8; nt++) {
            int col = j0 + nt * 8 + cbase;
            float2 b0 = *(const float2*)(brow0 + col);
            float2 b1 = *(const float2*)(brow1 + col);
            uint2 k0 = *(const uint2*)(mrow0 + col);
            uint2 k1 = *(const uint2*)(mrow1 + col);
            acc[nt][0] = k0.x ? acc[nt][0] + b0.x : -1e30f;
            acc[nt][1] = k0.y ? acc[nt][1] + b0.y : -1e30f;
            acc[nt][2] = k1.x ? acc[nt][2] + b1.x : -1e30f;
            acc[nt][3] = k1.y ? acc[nt][3] + b1.y : -1e30f;
            mx0 = fmaxf(mx0, fmaxf(acc[nt][0], acc[nt][1]));
            mx1 = fmaxf(mx1, fmaxf(acc[nt][2], acc[nt][3]));
        }
        mx0 = fmaxf(mx0, __shfl_xor_sync(0xffffffffu, mx0, 1));
        mx0 = fmaxf(mx0, __shfl_xor_sync(0xffffffffu, mx0, 2));
        mx1 = fmaxf(mx1, __shfl_xor_sync(0xffffffffu, mx1, 1));
        mx1 = fmaxf(mx1, __shfl_xor_sync(0xffffffffu, mx1, 2));

        float mn0 = fmaxf(m0, mx0), mn1 = fmaxf(m1, mx1);
        float a0 = __expf(m0 - mn0), a1 = __expf(m1 - mn1);
        m0 = mn0; m1 = mn1;

        float s0 = 0.0f, s1 = 0.0f;
#pragma unroll
        for (int nt = 0; nt < 8; nt++) {
            acc[nt][0] = __expf(acc[nt][0] - mn0);
            acc[nt][1] = __expf(acc[nt][1] - mn0);
            acc[nt][2] = __expf(acc[nt][2] - mn1);
            acc[nt][3] = __expf(acc[nt][3] - mn1);
            s0 += acc[nt][0] + acc[nt][1];
            s1 += acc[nt][2] + acc[nt][3];
        }
        s0 += __shfl_xor_sync(0xffffffffu, s0, 1);
        s0 += __shfl_xor_sync(0xffffffffu, s0, 2);
        s1 += __shfl_xor_sync(0xffffffffu, s1, 1);
        s1 += __shfl_xor_sync(0xffffffffu, s1, 2);
        l0 = l0 * a0 + s0;
        l1 = l1 * a1 + s1;

#pragma unroll
        for (int nt = 0; nt < 8; nt++) {
            Oacc[nt][0] *= a0; Oacc[nt][1] *= a0;
            Oacc[nt][2] *= a1; Oacc[nt][3] *= a1;
        }

        // ---- PV ----
#pragma unroll
        for (int kc = 0; kc < 4; kc++) {
            // P fragments for kv k-chunk kc (score n-tiles 2kc, 2kc+1)
            uint32_t pha[4], pla[4];
            {
                float p00 = acc[2 * kc][0],     p01 = acc[2 * kc][1];
                float p02 = acc[2 * kc][2],     p03 = acc[2 * kc][3];
                float p10 = acc[2 * kc + 1][0], p11 = acc[2 * kc + 1][1];
                float p12 = acc[2 * kc + 1][2], p13 = acc[2 * kc + 1][3];
                float h00 = __bfloat162float(__float2bfloat16(p00));
                float h01 = __bfloat162float(__float2bfloat16(p01));
                float h02 = __bfloat162float(__float2bfloat16(p02));
                float h03 = __bfloat162float(__float2bfloat16(p03));
                float h10 = __bfloat162float(__float2bfloat16(p10));
                float h11 = __bfloat162float(__float2bfloat16(p11));
                float h12 = __bfloat162float(__float2bfloat16(p12));
                float h13 = __bfloat162float(__float2bfloat16(p13));
                pha[0] = pack_bf16x2(h00, h01);
                pha[1] = pack_bf16x2(h02, h03);
                pha[2] = pack_bf16x2(h10, h11);
                pha[3] = pack_bf16x2(h12, h13);
                pla[0] = pack_bf16x2(p00 - h00, p01 - h01);
                pla[1] = pack_bf16x2(p02 - h02, p03 - h03);
                pla[2] = pack_bf16x2(p10 - h10, p11 - h11);
                pla[3] = pack_bf16x2(p12 - h12, p13 - h13);
            }
#pragma unroll
            for (int dp = 0; dp < 4; dp++) {
                int vrow = kc * 16 + (lane & 15);
                uint32_t voff = SMEM_SWZ(vrow * 128 + dp * 32 + (lane >> 4) * 16);
                uint32_t vh[4], vl[4];
                ldsm4t(vh, base + 16384 + voff);
                ldsm4t(vl, base + 24576 + voff);
                mma16816(Oacc[2 * dp],     pha, vh + 0);
                mma16816(Oacc[2 * dp],     pla, vh + 0);
                mma16816(Oacc[2 * dp],     pha, vl + 0);
                mma16816(Oacc[2 * dp + 1], pha, vh + 2);
                mma16816(Oacc[2 * dp + 1], pla, vh + 2);
                mma16816(Oacc[2 * dp + 1], pha, vl + 2);
            }
        }
        __syncthreads();
    }

    // ---- epilogue: normalize, split hi/lo, store ----
    float inv0 = 1.0f / l0, inv1 = 1.0f / l1;
#pragma unroll
    for (int nt = 0; nt < 8; nt++) {
        int col = hoff + nt * 8 + cbase;
        float v0 = Oacc[nt][0] * inv0, v1 = Oacc[nt][1] * inv0;
        float v2 = Oacc[nt][2] * inv1, v3 = Oacc[nt][3] * inv1;
        float h0 = __bfloat162float(__float2bfloat16(v0));
        float h1 = __bfloat162float(__float2bfloat16(v1));
        float h2 = __bfloat162float(__float2bfloat16(v2));
        float h3 = __bfloat162float(__float2bfloat16(v3));
        *(uint32_t*)(Oh_ + (size_t)grow0 * D_DIM + col) = pack_bf16x2(h0, h1);
        *(uint32_t*)(Oh_ + (size_t)grow1 * D_DIM + col) = pack_bf16x2(h2, h3);
        *(uint32_t*)(Ol_ + (size_t)grow0 * D_DIM + col) = pack_bf16x2(v0 - h0, v1 - h1);
        *(uint32_t*)(Ol_ + (size_t)grow1 * D_DIM + col) = pack_bf16x2(v2 - h2, v3 - h3);
    }
}

// ---------------------------------------------------------------------------
// LayerNorm
// ---------------------------------------------------------------------------
__device__ __forceinline__ float block_reduce_sum(float v) {
    __shared__ float red[8];
    int lane = threadIdx.x & 31, w = threadIdx.x >> 5;
#pragma unroll
    for (int o = 16; o > 0; o >>= 1) v += __shfl_xor_sync(0xffffffffu, v, o);
    __syncthreads();
    if (lane == 0) red[w] = v;
    __syncthreads();
    float t = 0.0f;
#pragma unroll
    for (int i = 0; i < 8; i++) t += red[i];
    return t;
}

__global__ __launch_bounds__(256) void ln_kernel(
    const float* __restrict__ res, const float* __restrict__ w,
    const float* __restrict__ b, float* __restrict__ out)
{
    int row = blockIdx.x;
    int tid = threadIdx.x;
    const float* r = res + (size_t)row * D_DIM;

    float4 x4 = *(const float4*)(r + tid * 4);
    float sum = x4.x + x4.y + x4.z + x4.w;
    sum = block_reduce_sum(sum);
    float mean = sum * (1.0f / D_DIM);

    float d0 = x4.x - mean, d1 = x4.y - mean, d2 = x4.z - mean, d3 = x4.w - mean;
    float sq = d0 * d0 + d1 * d1 + d2 * d2 + d3 * d3;
    sq = block_reduce_sum(sq);
    float inv = rsqrtf(sq * (1.0f / D_DIM) + LN_EPS);

    float4 w4 = *(const float4*)(w + tid * 4);
    float4 b4 = *(const float4*)(b + tid * 4);
    float4 o4;
    o4.x = d0 * inv * w4.x + b4.x;
    o4.y = d1 * inv * w4.y + b4.y;
    o4.z = d2 * inv * w4.z + b4.z;
    o4.w = d3 * inv * w4.w + b4.w;
    *(float4*)(out + (size_t)row * D_DIM + tid * 4) = o4;
}

// ---------------------------------------------------------------------------
// Launch
// ---------------------------------------------------------------------------
extern "C" void kernel_launch(void* const* d_in, const int* in_sizes, int n_in,
                              void* d_out, int out_size)
{
    (void)in_sizes; (void)n_in; (void)out_size;

    const float*        x    = (const float*)d_in[0];
    const float*        bias = (const float*)d_in[1];
    const unsigned int* mask = (const unsigned int*)d_in[2];
    const float*        Wq   = (const float*)d_in[3];
    const float*        Wk   = (const float*)d_in[4];
    const float*        Wv   = (const float*)d_in[5];
    const float*        Wo   = (const float*)d_in[6];
    const float*        lnw  = (const float*)d_in[7];
    const float*        lnb  = (const float*)d_in[8];
    float*              out  = (float*)d_out;

    void *pqh, *pql, *pkh, *pkl, *pvh, *pvl, *pxh, *pxl, *pah, *pal, *pwh, *pwl, *pres;
    cudaGetSymbolAddress(&pqh, g_qh); cudaGetSymbolAddress(&pql, g_ql);
    cudaGetSymbolAddress(&pkh, g_kh); cudaGetSymbolAddress(&pkl, g_kl);
    cudaGetSymbolAddress(&pvh, g_vh); cudaGetSymbolAddress(&pvl, g_vl);
    cudaGetSymbolAddress(&pxh, g_xh); cudaGetSymbolAddress(&pxl, g_xl);
    cudaGetSymbolAddress(&pah, g_ah); cudaGetSymbolAddress(&pal, g_al);
    cudaGetSymbolAddress(&pwh, g_wh); cudaGetSymbolAddress(&pwl, g_wl);
    cudaGetSymbolAddress(&pres, g_res);

    __nv_bfloat16 *qh = (__nv_bfloat16*)pqh, *ql = (__nv_bfloat16*)pql;
    __nv_bfloat16 *kh = (__nv_bfloat16*)pkh, *kl = (__nv_bfloat16*)pkl;
    __nv_bfloat16 *vh = (__nv_bfloat16*)pvh, *vl = (__nv_bfloat16*)pvl;
    __nv_bfloat16 *xh = (__nv_bfloat16*)pxh, *xl = (__nv_bfloat16*)pxl;
    __nv_bfloat16 *ah = (__nv_bfloat16*)pah, *al = (__nv_bfloat16*)pal;
    __nv_bfloat16 *wh = (__nv_bfloat16*)pwh, *wl = (__nv_bfloat16*)pwl;
    float* res = (float*)pres;

    cudaFuncSetAttribute(gemm_mma_kernel, cudaFuncAttributeMaxDynamicSharedMemorySize, GEMM_SMEM);
    cudaFuncSetAttribute(attn_mma_kernel, cudaFuncAttributeMaxDynamicSharedMemorySize, ATT_SMEM);

    const int nX = S_LEN * D_DIM;
    const int nW = D_DIM * D_DIM;
    dim3 gt(D_DIM / 128, S_LEN / 128);   // (8, 16)

    split_bf16_kernel<<<nX / 1024, 256>>>(x, xh, xl, nX);

    split_bf16_kernel<<<nW / 1024, 256>>>(Wq, wh, wl, nW);
    gemm_mma_kernel<<<gt, 256, GEMM_SMEM>>>(xh, xl, wh, wl, nullptr, nullptr,
                                            qh, ql, 0.125f, D_DIM, D_DIM);
    split_bf16_kernel<<<nW / 1024, 256>>>(Wk, wh, wl, nW);
    gemm_mma_kernel<<<gt, 256, GEMM_SMEM>>>(xh, xl, wh, wl, nullptr, nullptr,
                                            kh, kl, 1.0f, D_DIM, D_DIM);
    split_bf16_kernel<<<nW / 1024, 256>>>(Wv, wh, wl, nW);
    gemm_mma_kernel<<<gt, 256, GEMM_SMEM>>>(xh, xl, wh, wl, nullptr, nullptr,
                                            vh, vl, 1.0f, D_DIM, D_DIM);

    attn_mma_kernel<<<dim3(S_LEN / 128, H_NUM), 256, ATT_SMEM>>>(
        qh, ql, kh, kl, vh, vl, bias, mask, ah, al);

    split_bf16_kernel<<<nW / 1024, 256>>>(Wo, wh, wl, nW);
    gemm_mma_kernel<<<gt, 256, GEMM_SMEM>>>(ah, al, wh, wl, x, res,
                                            nullptr, nullptr, 1.0f, D_DIM, D_DIM);

    ln_kernel<<<S_LEN, 256>>>(res, lnw, lnb, out);
}

// round 5
// speedup vs baseline: 4.0954x; 1.1822x over previous
#include <cuda_runtime.h>
#include <cuda_bf16.h>
#include <cstdint>

// Problem constants
#define S_LEN 2048
#define D_DIM 1024
#define H_NUM 16
#define DH 64
#define LN_EPS 1e-5f
#define LOG2E 1.4426950408889634f

// ---------------------------------------------------------------------------
// PTX helpers (plain sm_103: ldmatrix + mma.sync + cp.async.bulk + mbarrier)
// ---------------------------------------------------------------------------
__device__ __forceinline__ uint32_t smem_u32(const void* p) {
    uint32_t a;
    asm("{ .reg .u64 t; cvta.to.shared.u64 t, %1; cvt.u32.u64 %0, t; }"
        : "=r"(a) : "l"(p));
    return a;
}

__device__ __forceinline__ void ldsm4(uint32_t* r, uint32_t a) {
    asm volatile("ldmatrix.sync.aligned.m8n8.x4.shared.b16 {%0,%1,%2,%3}, [%4];"
                 : "=r"(r[0]), "=r"(r[1]), "=r"(r[2]), "=r"(r[3]) : "r"(a));
}
__device__ __forceinline__ void ldsm4t(uint32_t* r, uint32_t a) {
    asm volatile("ldmatrix.sync.aligned.m8n8.x4.trans.shared.b16 {%0,%1,%2,%3}, [%4];"
                 : "=r"(r[0]), "=r"(r[1]), "=r"(r[2]), "=r"(r[3]) : "r"(a));
}

__device__ __forceinline__ void mma16816(float* c, const uint32_t* a, const uint32_t* b) {
    asm volatile("mma.sync.aligned.m16n8k16.row.col.f32.bf16.bf16.f32 "
                 "{%0,%1,%2,%3}, {%4,%5,%6,%7}, {%8,%9}, {%0,%1,%2,%3};"
                 : "+f"(c[0]), "+f"(c[1]), "+f"(c[2]), "+f"(c[3])
                 : "r"(a[0]), "r"(a[1]), "r"(a[2]), "r"(a[3]),
                   "r"(b[0]), "r"(b[1]));
}

#define MBARRIER_INIT(addr, cnt) \
    asm volatile("mbarrier.init.shared.b64 [%0], %1;" :: "r"((uint32_t)(addr)), "r"((uint32_t)(cnt)) : "memory")

#define MBARRIER_EXPECT_TX(addr, tx) \
    asm volatile("mbarrier.arrive.expect_tx.shared.b64 _, [%0], %1;" \
                 :: "r"((uint32_t)(addr)), "r"((uint32_t)(tx)) : "memory")

#define MBARRIER_WAIT_PARITY(mbar_smem_addr, phase_parity) do { \
    uint32_t _mbar = (uint32_t)(mbar_smem_addr); \
    uint32_t _parity = (uint32_t)(phase_parity); \
    uint32_t _done; \
    asm volatile("{\n\t.reg .pred p;\n\t" \
        "mbarrier.try_wait.parity.acquire.cta.shared::cta.b64 p, [%1], %2;\n\t" \
        "selp.b32 %0, 1, 0, p;\n\t}" \
        : "=r"(_done) : "r"(_mbar), "r"(_parity) : "memory"); \
    if (!_done) { \
        asm volatile("{\n\t.reg .pred P1;\n\t" \
            "WAIT_LOOP_%=:\n\t" \
            "mbarrier.try_wait.parity.acquire.cta.shared::cta.b64 P1, [%0], %1, 0x989680;\n\t" \
            "@P1 bra.uni WAIT_DONE_%=;\n\t" \
            "bra.uni WAIT_LOOP_%=;\n\t" \
            "WAIT_DONE_%=:\n\t}" \
            :: "r"(_mbar), "r"(_parity) : "memory"); \
    } \
} while (0)

__device__ __forceinline__ void bulk_g2s(uint32_t dst, const void* src, uint32_t bytes, uint32_t mbar) {
    asm volatile("cp.async.bulk.shared::cluster.global.mbarrier::complete_tx::bytes "
                 "[%0], [%1], %2, [%3];"
                 :: "r"(dst), "l"(src), "r"(bytes), "r"(mbar) : "memory");
}

#define FENCE_PROXY_ASYNC() asm volatile("fence.proxy.async.shared::cta;" ::: "memory")

#define SMEM_SWZ(off) ((off) ^ (((off) >> 3) & 0x70))

__device__ __forceinline__ uint32_t pack_bf16x2(float a, float b) {
    __nv_bfloat162 t = __floats2bfloat162_rn(a, b);
    return *reinterpret_cast<uint32_t*>(&t);
}
__device__ __forceinline__ void split2(float a, float b, uint32_t& hi, uint32_t& lo) {
    float ha = __bfloat162float(__float2bfloat16(a));
    float hb = __bfloat162float(__float2bfloat16(b));
    hi = pack_bf16x2(ha, hb);
    lo = pack_bf16x2(a - ha, b - hb);
}
__device__ __forceinline__ float ex2(float x) {
    float y; asm("ex2.approx.ftz.f32 %0, %1;" : "=f"(y) : "f"(x)); return y;
}

// ---------------------------------------------------------------------------
// Scratch (device globals). All blob layouts are pre-swizzled SW128 tiles.
//  GEMM A/B blob: [rb(128 rows)][kc(64 cols)] -> 32KB = hi 16KB + lo 16KB
//  Q blob:  [qb(128 rows)][head] -> 32KB = Qh 16KB + Ql 16KB
//  KV blob: [head][kvt(64 rows)] -> 32KB = Kh 8KB + Kl 8KB + Vh 8KB + Vl 8KB
// ---------------------------------------------------------------------------
__device__ __align__(128) __nv_bfloat16 g_xb [2 * S_LEN * D_DIM];
__device__ __align__(128) __nv_bfloat16 g_wqb[2 * D_DIM * D_DIM];
__device__ __align__(128) __nv_bfloat16 g_wkb[2 * D_DIM * D_DIM];
__device__ __align__(128) __nv_bfloat16 g_wvb[2 * D_DIM * D_DIM];
__device__ __align__(128) __nv_bfloat16 g_wob[2 * D_DIM * D_DIM];
__device__ __align__(128) __nv_bfloat16 g_qb [2 * S_LEN * D_DIM];
__device__ __align__(128) __nv_bfloat16 g_kvb[4 * S_LEN * D_DIM];
__device__ __align__(128) __nv_bfloat16 g_ab [2 * S_LEN * D_DIM];
__device__ float g_res[S_LEN * D_DIM];

// ---------------------------------------------------------------------------
// Fused split: fp32 row-major -> hi/lo blob layout, all 5 sources, 1 launch.
// Each thread handles 8 consecutive cols of one row.
// grid.x: [0,1024) -> x (2048 rows); [1024+512w, ...) -> W_w (1024 rows)
// ---------------------------------------------------------------------------
__global__ __launch_bounds__(256) void split_all_kernel(
    const float* __restrict__ x,
    const float* __restrict__ Wq, const float* __restrict__ Wk,
    const float* __restrict__ Wv, const float* __restrict__ Wo,
    __nv_bfloat16* __restrict__ xb,
    __nv_bfloat16* __restrict__ wqb, __nv_bfloat16* __restrict__ wkb,
    __nv_bfloat16* __restrict__ wvb, __nv_bfloat16* __restrict__ wob)
{
    int bid = blockIdx.x;
    const float* src;
    __nv_bfloat16* dst;
    int lbid;
    if (bid < 1024) { src = x; dst = xb; lbid = bid; }
    else {
        int w = (bid - 1024) >> 9;
        lbid = (bid - 1024) & 511;
        src = (w == 0) ? Wq : (w == 1) ? Wk : (w == 2) ? Wv : Wo;
        dst = (w == 0) ? wqb : (w == 1) ? wkb : (w == 2) ? wvb : wob;
    }
    int idx = lbid * 256 + threadIdx.x;
    int row = idx >> 7;          // 128 col-groups per row
    int k   = (idx & 127) * 8;   // 8 cols per group

    float4 v0 = *(const float4*)(src + (size_t)row * D_DIM + k);
    float4 v1 = *(const float4*)(src + (size_t)row * D_DIM + k + 4);

    uint4 hi, lo;
    uint32_t h, l;
    split2(v0.x, v0.y, h, l); hi.x = h; lo.x = l;
    split2(v0.z, v0.w, h, l); hi.y = h; lo.y = l;
    split2(v1.x, v1.y, h, l); hi.z = h; lo.z = l;
    split2(v1.z, v1.w, h, l); hi.w = h; lo.w = l;

    size_t base = ((size_t)(row >> 7) * 16 + (k >> 6)) * 32768;
    uint32_t off = SMEM_SWZ((uint32_t)((row & 127) * 128 + (k & 63) * 2));
    char* p = (char*)dst + base;
    *(uint4*)(p + off) = hi;
    *(uint4*)(p + 16384 + off) = lo;
}

// ---------------------------------------------------------------------------
// Blob GEMM via cp.async.bulk: C[m,n] = scale * sum_k A[m,k]*B[n,k]
// Tile 128x128, BK=64, 3-stage bulk pipeline. 8 warps (2x4), warp = 64x32.
// modes: 0 = fp32 (+resid) row-major; 1 = Q blob; 2 = K blob; 3 = V blob
// ---------------------------------------------------------------------------
#define GEMM_SMEM (64 + 3 * 65536)

__global__ __launch_bounds__(256) void gemm_blob_kernel(
    const __nv_bfloat16* __restrict__ Ablob, const __nv_bfloat16* __restrict__ Bblob,
    const float* __restrict__ resid, float* __restrict__ Cf,
    __nv_bfloat16* __restrict__ OutB, int mode, float scale, int N, int K)
{
    extern __shared__ char smem[];
    const uint32_t sb = smem_u32(smem);
    const int tid  = threadIdx.x;
    const int wid  = tid >> 5;
    const int lane = tid & 31;
    const int wm   = wid >> 2;
    const int wn   = wid & 3;

    const int mb = blockIdx.y, nb = blockIdx.x;
    const int m0 = mb * 128, n0 = nb * 128;
    const int NCH = K >> 6;   // 16

    const char* Asrc = (const char*)Ablob + (size_t)mb * NCH * 32768;
    const char* Bsrc = (const char*)Bblob + (size_t)nb * NCH * 32768;

    if (tid == 0) {
        MBARRIER_INIT(sb + 0, 1);
        MBARRIER_INIT(sb + 8, 1);
        MBARRIER_INIT(sb + 16, 1);
        FENCE_PROXY_ASYNC();
    }
    __syncthreads();

    if (tid == 0) {
#pragma unroll
        for (int s = 0; s < 3; s++) {
            uint32_t mbar = sb + 8 * s;
            uint32_t dst = sb + 64 + s * 65536;
            MBARRIER_EXPECT_TX(mbar, 65536);
            bulk_g2s(dst,         Asrc + (size_t)s * 32768, 32768, mbar);
            bulk_g2s(dst + 32768, Bsrc + (size_t)s * 32768, 32768, mbar);
        }
    }

    float acc[4][4][4];
#pragma unroll
    for (int i = 0; i < 4; i++)
#pragma unroll
        for (int j = 0; j < 4; j++)
#pragma unroll
            for (int r = 0; r < 4; r++) acc[i][j][r] = 0.0f;

    const int arow = wm * 64 + (lane & 15);
    const int brow = wn * 32 + ((lane >> 4) & 1) * 8 + (lane & 7);

    for (int ch = 0; ch < NCH; ch++) {
        const int s = ch % 3;
        MBARRIER_WAIT_PARITY(sb + 8 * s, (ch / 3) & 1);

        const uint32_t bufA = sb + 64 + s * 65536;
        const uint32_t bufB = bufA + 32768;

#pragma unroll
        for (int kc = 0; kc < 4; kc++) {
            uint32_t ah[4][4], alr[4][4], bh[4][2], bl[4][2];
#pragma unroll
            for (int mt = 0; mt < 4; mt++) {
                uint32_t off = SMEM_SWZ((uint32_t)((arow + mt * 16) * 128 + kc * 32 + (lane >> 4) * 16));
                ldsm4(ah[mt],  bufA + off);
                ldsm4(alr[mt], bufA + 16384 + off);
            }
#pragma unroll
            for (int np = 0; np < 2; np++) {
                uint32_t off = SMEM_SWZ((uint32_t)((brow + np * 16) * 128 + kc * 32 + ((lane >> 3) & 1) * 16));
                uint32_t r[4];
                ldsm4(r, bufB + off);
                bh[np * 2][0] = r[0]; bh[np * 2][1] = r[1];
                bh[np * 2 + 1][0] = r[2]; bh[np * 2 + 1][1] = r[3];
                ldsm4(r, bufB + 16384 + off);
                bl[np * 2][0] = r[0]; bl[np * 2][1] = r[1];
                bl[np * 2 + 1][0] = r[2]; bl[np * 2 + 1][1] = r[3];
            }
#pragma unroll
            for (int mt = 0; mt < 4; mt++)
#pragma unroll
                for (int nt = 0; nt < 4; nt++) {
                    mma16816(acc[mt][nt], ah[mt],  bh[nt]);
                    mma16816(acc[mt][nt], ah[mt],  bl[nt]);
                    mma16816(acc[mt][nt], alr[mt], bh[nt]);
                }
        }
        __syncthreads();

        if (ch + 3 < NCH && tid == 0) {
            uint32_t mbar = sb + 8 * s;
            uint32_t dst = sb + 64 + s * 65536;
            MBARRIER_EXPECT_TX(mbar, 65536);
            bulk_g2s(dst,         Asrc + (size_t)(ch + 3) * 32768, 32768, mbar);
            bulk_g2s(dst + 32768, Bsrc + (size_t)(ch + 3) * 32768, 32768, mbar);
        }
    }

    // Epilogue
#pragma unroll
    for (int mt = 0; mt < 4; mt++) {
        int row = m0 + wm * 64 + mt * 16 + (lane >> 2);
#pragma unroll
        for (int nt = 0; nt < 4; nt++) {
            int col = n0 + wn * 32 + nt * 8 + (lane & 3) * 2;
            float v0 = acc[mt][nt][0] * scale;
            float v1 = acc[mt][nt][1] * scale;
            float v2 = acc[mt][nt][2] * scale;
            float v3 = acc[mt][nt][3] * scale;
            if (mode == 0) {
                if (resid) {
                    float2 r0 = *(const float2*)(resid + (size_t)row * N + col);
                    float2 r1 = *(const float2*)(resid + (size_t)(row + 8) * N + col);
                    v0 += r0.x; v1 += r0.y; v2 += r1.x; v3 += r1.y;
                }
                *(float2*)(Cf + (size_t)row * N + col) = make_float2(v0, v1);
                *(float2*)(Cf + (size_t)(row + 8) * N + col) = make_float2(v2, v3);
            } else {
                uint32_t h01, l01, h23, l23;
                split2(v0, v1, h01, l01);
                split2(v2, v3, h23, l23);
                if (mode == 1) {
                    size_t base = ((size_t)(row >> 7) * 16 + (col >> 6)) * 32768;
                    uint32_t o0 = SMEM_SWZ((uint32_t)((row & 127) * 128 + (col & 63) * 2));
                    uint32_t o1 = SMEM_SWZ((uint32_t)(((row + 8) & 127) * 128 + (col & 63) * 2));
                    char* p = (char*)OutB + base;
                    *(uint32_t*)(p + o0) = h01; *(uint32_t*)(p + 16384 + o0) = l01;
                    *(uint32_t*)(p + o1) = h23; *(uint32_t*)(p + 16384 + o1) = l23;
                } else {
                    size_t base = ((size_t)(col >> 6) * 32 + (row >> 6)) * 32768
                                  + (mode == 3 ? 16384 : 0);
                    uint32_t o0 = SMEM_SWZ((uint32_t)((row & 63) * 128 + (col & 63) * 2));
                    uint32_t o1 = SMEM_SWZ((uint32_t)(((row + 8) & 63) * 128 + (col & 63) * 2));
                    char* p = (char*)OutB + base;
                    *(uint32_t*)(p + o0) = h01; *(uint32_t*)(p + 8192 + o0) = l01;
                    *(uint32_t*)(p + o1) = h23; *(uint32_t*)(p + 8192 + o1) = l23;
                }
            }
        }
    }
}

// ---------------------------------------------------------------------------
// Tensor-core flash attention with bulk KV loads.
// Grid (16, 16): 128 q-rows x head. 8 warps, each 16 q rows.
// KV ring: 4 x 32KB blobs ({Kh,Kl,Vh,Vl} x 64 rows). Q staged once (32KB).
// Scores are in log2 domain (Q pre-scaled by 0.125*log2e at projection).
// Output -> attn-out blob (A-operand layout for the Wo GEMM, kc == head).
// ---------------------------------------------------------------------------
#define ATT_SMEM (64 + 32768 + 4 * 32768)

__global__ __launch_bounds__(256, 1) void attn_blob_kernel(
    const __nv_bfloat16* __restrict__ Qb, const __nv_bfloat16* __restrict__ KVb,
    const float* __restrict__ bias, const unsigned int* __restrict__ mask,
    __nv_bfloat16* __restrict__ Ob)
{
    extern __shared__ char smem[];
    const uint32_t sb = smem_u32(smem);
    const uint32_t qsm  = sb + 64;
    const uint32_t kvsm = sb + 64 + 32768;
    const int tid  = threadIdx.x;
    const int wid  = tid >> 5;
    const int lane = tid & 31;
    const int h  = blockIdx.y;
    const int qb = blockIdx.x;
    const int q0 = qb * 128;

    const char* Qsrc  = (const char*)Qb + ((size_t)qb * 16 + h) * 32768;
    const char* KVsrc = (const char*)KVb + (size_t)h * 32 * 32768;

    if (tid == 0) {
        MBARRIER_INIT(sb + 0, 1);                      // Q
#pragma unroll
        for (int i = 0; i < 4; i++) MBARRIER_INIT(sb + 8 + 8 * i, 1);
        FENCE_PROXY_ASYNC();
    }
    __syncthreads();

    if (tid == 0) {
        MBARRIER_EXPECT_TX(sb + 0, 32768);
        bulk_g2s(qsm, Qsrc, 32768, sb + 0);
#pragma unroll
        for (int i = 0; i < 4; i++) {
            MBARRIER_EXPECT_TX(sb + 8 + 8 * i, 32768);
            bulk_g2s(kvsm + i * 32768, KVsrc + (size_t)i * 32768, 32768, sb + 8 + 8 * i);
        }
    }

    MBARRIER_WAIT_PARITY(sb + 0, 0);

    // Q fragments
    uint32_t qh[4][4], ql[4][4];
    {
        const int qrow = wid * 16 + (lane & 15);
#pragma unroll
        for (int kc = 0; kc < 4; kc++) {
            uint32_t off = SMEM_SWZ((uint32_t)(qrow * 128 + kc * 32 + (lane >> 4) * 16));
            ldsm4(qh[kc], qsm + off);
            ldsm4(ql[kc], qsm + 16384 + off);
        }
    }

    float Oacc[8][4];
#pragma unroll
    for (int i = 0; i < 8; i++)
#pragma unroll
        for (int j = 0; j < 4; j++) Oacc[i][j] = 0.0f;
    float m0 = -1e30f, m1 = -1e30f, l0 = 0.0f, l1 = 0.0f;

    const int r = lane >> 2;
    const int grow0 = q0 + wid * 16 + r;
    const int grow1 = grow0 + 8;
    const float* brow0 = bias + (size_t)grow0 * (H_NUM * S_LEN) + (size_t)h * S_LEN;
    const float* brow1 = bias + (size_t)grow1 * (H_NUM * S_LEN) + (size_t)h * S_LEN;
    const unsigned int* mrow0 = mask + (size_t)grow0 * S_LEN;
    const unsigned int* mrow1 = mask + (size_t)grow1 * S_LEN;
    const int cbase = (lane & 3) * 2;

    for (int t = 0; t < S_LEN / 64; t++) {
        MBARRIER_WAIT_PARITY(sb + 8 + 8 * (t & 3), (t >> 2) & 1);
        const uint32_t base = kvsm + (t & 3) * 32768;
        const int j0 = t * 64;

        // scores
        float acc[8][4];
#pragma unroll
        for (int i = 0; i < 8; i++)
#pragma unroll
            for (int j = 0; j < 4; j++) acc[i][j] = 0.0f;

#pragma unroll
        for (int kc = 0; kc < 4; kc++) {
#pragma unroll
            for (int np = 0; np < 4; np++) {
                int krow = np * 16 + (lane >> 4) * 8 + (lane & 7);
                uint32_t koff = SMEM_SWZ((uint32_t)(krow * 128 + kc * 32 + ((lane >> 3) & 1) * 16));
                uint32_t bh[4], bl[4];
                ldsm4(bh, base + koff);
                ldsm4(bl, base + 8192 + koff);
                mma16816(acc[2 * np],     qh[kc], bh + 0);
                mma16816(acc[2 * np],     qh[kc], bl + 0);
                mma16816(acc[2 * np],     ql[kc], bh + 0);
                mma16816(acc[2 * np + 1], qh[kc], bh + 2);
                mma16816(acc[2 * np + 1], qh[kc], bl + 2);
                mma16816(acc[2 * np + 1], ql[kc], bh + 2);
            }
        }

        // bias + mask + row max (log2 domain)
        float mx0 = -1e30f, mx1 = -1e30f;
#pragma unroll
        for (int nt = 0; nt < 8; nt++) {
            int col = j0 + nt * 8 + cbase;
            float2 b0 = *(const float2*)(brow0 + col);
            float2 b1 = *(const float2*)(brow1 + col);
            uint2 k0 = *(const uint2*)(mrow0 + col);
            uint2 k1 = *(const uint2*)(mrow1 + col);
            acc[nt][0] = k0.x ? fmaf(b0.x, LOG2E, acc[nt][0]) : -1e30f;
            acc[nt][1] = k0.y ? fmaf(b0.y, LOG2E, acc[nt][1]) : -1e30f;
            acc[nt][2] = k1.x ? fmaf(b1.x, LOG2E, acc[nt][2]) : -1e30f;
            acc[nt][3] = k1.y ? fmaf(b1.y, LOG2E, acc[nt][3]) : -1e30f;
            mx0 = fmaxf(mx0, fmaxf(acc[nt][0], acc[nt][1]));
            mx1 = fmaxf(mx1, fmaxf(acc[nt][2], acc[nt][3]));
        }
        mx0 = fmaxf(mx0, __shfl_xor_sync(0xffffffffu, mx0, 1));
        mx0 = fmaxf(mx0, __shfl_xor_sync(0xffffffffu, mx0, 2));
        mx1 = fmaxf(mx1, __shfl_xor_sync(0xffffffffu, mx1, 1));
        mx1 = fmaxf(mx1, __shfl_xor_sync(0xffffffffu, mx1, 2));

        float mn0 = fmaxf(m0, mx0), mn1 = fmaxf(m1, mx1);
        float a0 = ex2(m0 - mn0), a1 = ex2(m1 - mn1);
        m0 = mn0; m1 = mn1;

        float s0 = 0.0f, s1 = 0.0f;
#pragma unroll
        for (int nt = 0; nt < 8; nt++) {
            acc[nt][0] = ex2(acc[nt][0] - mn0);
            acc[nt][1] = ex2(acc[nt][1] - mn0);
            acc[nt][2] = ex2(acc[nt][2] - mn1);
            acc[nt][3] = ex2(acc[nt][3] - mn1);
            s0 += acc[nt][0] + acc[nt][1];
            s1 += acc[nt][2] + acc[nt][3];
        }
        s0 += __shfl_xor_sync(0xffffffffu, s0, 1);
        s0 += __shfl_xor_sync(0xffffffffu, s0, 2);
        s1 += __shfl_xor_sync(0xffffffffu, s1, 1);
        s1 += __shfl_xor_sync(0xffffffffu, s1, 2);
        l0 = l0 * a0 + s0;
        l1 = l1 * a1 + s1;

#pragma unroll
        for (int nt = 0; nt < 8; nt++) {
            Oacc[nt][0] *= a0; Oacc[nt][1] *= a0;
            Oacc[nt][2] *= a1; Oacc[nt][3] *= a1;
        }

        // PV
#pragma unroll
        for (int kc = 0; kc < 4; kc++) {
            uint32_t pha[4], pla[4];
            {
                float p00 = acc[2 * kc][0],     p01 = acc[2 * kc][1];
                float p02 = acc[2 * kc][2],     p03 = acc[2 * kc][3];
                float p10 = acc[2 * kc + 1][0], p11 = acc[2 * kc + 1][1];
                float p12 = acc[2 * kc + 1][2], p13 = acc[2 * kc + 1][3];
                split2(p00, p01, pha[0], pla[0]);
                split2(p02, p03, pha[1], pla[1]);
                split2(p10, p11, pha[2], pla[2]);
                split2(p12, p13, pha[3], pla[3]);
            }
#pragma unroll
            for (int dp = 0; dp < 4; dp++) {
                int vrow = kc * 16 + (lane & 15);
                uint32_t voff = SMEM_SWZ((uint32_t)(vrow * 128 + dp * 32 + (lane >> 4) * 16));
                uint32_t vh[4], vl[4];
                ldsm4t(vh, base + 16384 + voff);
                ldsm4t(vl, base + 24576 + voff);
                mma16816(Oacc[2 * dp],     pha, vh + 0);
                mma16816(Oacc[2 * dp],     pla, vh + 0);
                mma16816(Oacc[2 * dp],     pha, vl + 0);
                mma16816(Oacc[2 * dp + 1], pha, vh + 2);
                mma16816(Oacc[2 * dp + 1], pla, vh + 2);
                mma16816(Oacc[2 * dp + 1], pha, vl + 2);
            }
        }
        __syncthreads();

        if (t + 4 < S_LEN / 64 && tid == 0) {
            uint32_t mbar = sb + 8 + 8 * (t & 3);
            MBARRIER_EXPECT_TX(mbar, 32768);
            bulk_g2s(kvsm + (t & 3) * 32768, KVsrc + (size_t)(t + 4) * 32768, 32768, mbar);
        }
    }

    // epilogue -> attn-out blob (qb, kc=h)
    float inv0 = 1.0f / l0, inv1 = 1.0f / l1;
    char* outb = (char*)Ob + ((size_t)qb * 16 + h) * 32768;
    const int r128 = wid * 16 + r;
#pragma unroll
    for (int nt = 0; nt < 8; nt++) {
        int d = nt * 8 + cbase;
        float v0 = Oacc[nt][0] * inv0, v1 = Oacc[nt][1] * inv0;
        float v2 = Oacc[nt][2] * inv1, v3 = Oacc[nt][3] * inv1;
        uint32_t h01, l01, h23, l23;
        split2(v0, v1, h01, l01);
        split2(v2, v3, h23, l23);
        uint32_t o0 = SMEM_SWZ((uint32_t)(r128 * 128 + d * 2));
        uint32_t o1 = SMEM_SWZ((uint32_t)((r128 + 8) * 128 + d * 2));
        *(uint32_t*)(outb + o0) = h01; *(uint32_t*)(outb + 16384 + o0) = l01;
        *(uint32_t*)(outb + o1) = h23; *(uint32_t*)(outb + 16384 + o1) = l23;
    }
}

// ---------------------------------------------------------------------------
// LayerNorm
// ---------------------------------------------------------------------------
__device__ __forceinline__ float block_reduce_sum(float v) {
    __shared__ float red[8];
    int lane = threadIdx.x & 31, w = threadIdx.x >> 5;
#pragma unroll
    for (int o = 16; o > 0; o >>= 1) v += __shfl_xor_sync(0xffffffffu, v, o);
    __syncthreads();
    if (lane == 0) red[w] = v;
    __syncthreads();
    float t = 0.0f;
#pragma unroll
    for (int i = 0; i < 8; i++) t += red[i];
    return t;
}

__global__ __launch_bounds__(256) void ln_kernel(
    const float* __restrict__ res, const float* __restrict__ w,
    const float* __restrict__ b, float* __restrict__ out)
{
    int row = blockIdx.x;
    int tid = threadIdx.x;
    const float* r = res + (size_t)row * D_DIM;

    float4 x4 = *(const float4*)(r + tid * 4);
    float sum = x4.x + x4.y + x4.z + x4.w;
    sum = block_reduce_sum(sum);
    float mean = sum * (1.0f / D_DIM);

    float d0 = x4.x - mean, d1 = x4.y - mean, d2 = x4.z - mean, d3 = x4.w - mean;
    float sq = d0 * d0 + d1 * d1 + d2 * d2 + d3 * d3;
    sq = block_reduce_sum(sq);
    float inv = rsqrtf(sq * (1.0f / D_DIM) + LN_EPS);

    float4 w4 = *(const float4*)(w + tid * 4);
    float4 b4 = *(const float4*)(b + tid * 4);
    float4 o4;
    o4.x = d0 * inv * w4.x + b4.x;
    o4.y = d1 * inv * w4.y + b4.y;
    o4.z = d2 * inv * w4.z + b4.z;
    o4.w = d3 * inv * w4.w + b4.w;
    *(float4*)(out + (size_t)row * D_DIM + tid * 4) = o4;
}

// ---------------------------------------------------------------------------
// Launch
// ---------------------------------------------------------------------------
extern "C" void kernel_launch(void* const* d_in, const int* in_sizes, int n_in,
                              void* d_out, int out_size)
{
    (void)in_sizes; (void)n_in; (void)out_size;

    const float*        x    = (const float*)d_in[0];
    const float*        bias = (const float*)d_in[1];
    const unsigned int* mask = (const unsigned int*)d_in[2];
    const float*        Wq   = (const float*)d_in[3];
    const float*        Wk   = (const float*)d_in[4];
    const float*        Wv   = (const float*)d_in[5];
    const float*        Wo   = (const float*)d_in[6];
    const float*        lnw  = (const float*)d_in[7];
    const float*        lnb  = (const float*)d_in[8];
    float*              out  = (float*)d_out;

    void *pxb, *pwq, *pwk, *pwv, *pwo, *pqb, *pkv, *pab, *pres;
    cudaGetSymbolAddress(&pxb, g_xb);
    cudaGetSymbolAddress(&pwq, g_wqb);
    cudaGetSymbolAddress(&pwk, g_wkb);
    cudaGetSymbolAddress(&pwv, g_wvb);
    cudaGetSymbolAddress(&pwo, g_wob);
    cudaGetSymbolAddress(&pqb, g_qb);
    cudaGetSymbolAddress(&pkv, g_kvb);
    cudaGetSymbolAddress(&pab, g_ab);
    cudaGetSymbolAddress(&pres, g_res);

    __nv_bfloat16 *xb = (__nv_bfloat16*)pxb;
    __nv_bfloat16 *wqb = (__nv_bfloat16*)pwq, *wkb = (__nv_bfloat16*)pwk;
    __nv_bfloat16 *wvb = (__nv_bfloat16*)pwv, *wob = (__nv_bfloat16*)pwo;
    __nv_bfloat16 *qb = (__nv_bfloat16*)pqb, *kvb = (__nv_bfloat16*)pkv;
    __nv_bfloat16 *ab = (__nv_bfloat16*)pab;
    float* res = (float*)pres;

    cudaFuncSetAttribute(gemm_blob_kernel, cudaFuncAttributeMaxDynamicSharedMemorySize, GEMM_SMEM);
    cudaFuncSetAttribute(attn_blob_kernel, cudaFuncAttributeMaxDynamicSharedMemorySize, ATT_SMEM);

    dim3 gt(D_DIM / 128, S_LEN / 128);   // (8, 16)

    // All 5 splits in one launch: 1024 + 4*512 = 3072 blocks
    split_all_kernel<<<3072, 256>>>(x, Wq, Wk, Wv, Wo, xb, wqb, wkb, wvb, wob);

    // Projections (Q pre-scaled by 1/sqrt(64) * log2(e))
    gemm_blob_kernel<<<gt, 256, GEMM_SMEM>>>(xb, wqb, nullptr, nullptr, qb,
                                             1, 0.125f * LOG2E, D_DIM, D_DIM);
    gemm_blob_kernel<<<gt, 256, GEMM_SMEM>>>(xb, wkb, nullptr, nullptr, kvb,
                                             2, 1.0f, D_DIM, D_DIM);
    gemm_blob_kernel<<<gt, 256, GEMM_SMEM>>>(xb, wvb, nullptr, nullptr, kvb,
                                             3, 1.0f, D_DIM, D_DIM);

    // Attention
    attn_blob_kernel<<<dim3(S_LEN / 128, H_NUM), 256, ATT_SMEM>>>(qb, kvb, bias, mask, ab);

    // Output projection + residual
    gemm_blob_kernel<<<gt, 256, GEMM_SMEM>>>(ab, wob, x, res, nullptr,
                                             0, 1.0f, D_DIM, D_DIM);

    ln_kernel<<<S_LEN, 256>>>(res, lnw, lnb, out);
}